// round 17
// baseline (speedup 1.0000x reference)
#include <cuda_runtime.h>
#include <math.h>

// ---------------------------------------------------------------------------
// VQ-VAE 3D forward, round 15: voxel-register-tiled (4 voxels x 8 Cout per
// thread) so weight LDS is amortized 4x -> FMA-pipe bound instead of LDS bound.
// ---------------------------------------------------------------------------

// scratch (allocation-free: __device__ globals)
__device__ float g_h1[4 * 16 * 64 * 64 * 64];   // 67 MB
__device__ float g_h2[4 * 32 * 32 * 32 * 32];   // 16.8 MB
__device__ float g_d1[4 * 32 * 32 * 32 * 32];   // 16.8 MB
__device__ float g_d2[4 * 16 * 64 * 64 * 64];   // 67 MB
__device__ float g_wT[328704];                  // transposed weights

// g_wT layout offsets (floats):
//   w1T  @ 0       size 1024    [ci=1 ][64][co=16]
//   w2T  @ 1024    size 32768   [ci=16][64][co=32]
//   w3T  @ 33792   size 131072  [ci=32][64][co=64]
//   dw1T @ 164864  size 131072  [ci=64][64][co=32]
//   dw2T @ 295936  size 32768   [ci=32][64][co=16]

// ---------------------------------------------------------------------------
// weight transposes: conv (OIDHW: w[co][ci][tap]) and convT (w[ci][co][tap])
// both -> wT[ci][tap][co]
// ---------------------------------------------------------------------------
__global__ void transp_oihw(const float* __restrict__ w, float* __restrict__ o,
                            int CIN, int COUT)
{
    int idx = blockIdx.x * 256 + threadIdx.x;
    if (idx >= CIN * COUT * 64) return;
    int co = idx / (CIN * 64);
    int r  = idx - co * CIN * 64;
    int ci = r >> 6, tap = r & 63;
    o[(ci * 64 + tap) * COUT + co] = w[idx];
}

__global__ void transp_iohw(const float* __restrict__ w, float* __restrict__ o,
                            int CIN, int COUT)
{
    int idx = blockIdx.x * 256 + threadIdx.x;
    if (idx >= CIN * COUT * 64) return;
    int ci = idx / (COUT * 64);
    int r  = idx - ci * COUT * 64;
    int co = r >> 6, tap = r & 63;
    o[(ci * 64 + tap) * COUT + co] = w[idx];
}

// ---------------------------------------------------------------------------
// strided conv k4 s2 p1. Thread computes VT=OUTS/Q voxels (ow = q + Q*v) for
// 8 output channels (co = cg + CG*i). Block = Q*CG*OH_T threads, warp-uniform
// ohi -> conflict-free patch broadcast; co consecutive -> conflict-free wsm.
// ---------------------------------------------------------------------------
template <int CIN, int COUT, int INS, int OUTS, int CG, int Q, int OH_T, bool RELU>
__global__ void __launch_bounds__(Q * CG * OH_T) conv_k(
    const float* __restrict__ x, const float* __restrict__ wT,
    const float* __restrict__ b, float* __restrict__ y)
{
    constexpr int NT = Q * CG * OH_T;
    constexpr int VT = OUTS / Q;
    constexpr int IH = 2 * OH_T + 2;
    constexpr int PW = 2 * OUTS + 2;

    __shared__ float wsm[64 * COUT];        // [tap][co]
    __shared__ float patch[4 * IH * PW];    // [kd][ih][iw+1]

    const int od = blockIdx.x, oh0 = blockIdx.y * OH_T, n = blockIdx.z;
    const int t = threadIdx.x;
    const int q = t % Q;
    const int cg = (t / Q) % CG;
    const int ohi = t / (Q * CG);

    float acc[VT][8];
#pragma unroll
    for (int v = 0; v < VT; v++)
#pragma unroll
        for (int i = 0; i < 8; i++) acc[v][i] = b[cg + CG * i];

    for (int ci = 0; ci < CIN; ci++) {
        __syncthreads();
        for (int idx = t; idx < 64 * COUT; idx += NT)
            wsm[idx] = wT[ci * 64 * COUT + idx];
        const float* xs = x + (size_t)(n * CIN + ci) * INS * INS * INS;
        for (int idx = t; idx < 4 * IH * PW; idx += NT) {
            int kd = idx / (IH * PW);
            int r  = (idx / PW) % IH;
            int j  = idx % PW;
            int id = 2 * od - 1 + kd;
            int ih = 2 * oh0 - 1 + r;
            int iw = j - 1;
            float v = 0.f;
            if ((unsigned)id < (unsigned)INS && (unsigned)ih < (unsigned)INS &&
                (unsigned)iw < (unsigned)INS)
                v = xs[(id * INS + ih) * INS + iw];
            patch[idx] = v;
        }
        __syncthreads();

#pragma unroll 1
        for (int kd = 0; kd < 4; kd++) {
#pragma unroll
            for (int kh = 0; kh < 4; kh++) {
                const float* prow = patch + (kd * IH + 2 * ohi + kh) * PW;
#pragma unroll
                for (int kw = 0; kw < 4; kw++) {
                    float pv[VT];
#pragma unroll
                    for (int v = 0; v < VT; v++)
                        pv[v] = prow[2 * (q + Q * v) + kw];
                    const float* wrow = wsm + ((kd * 4 + kh) * 4 + kw) * COUT + cg;
                    float wv[8];
#pragma unroll
                    for (int i = 0; i < 8; i++) wv[i] = wrow[CG * i];
#pragma unroll
                    for (int v = 0; v < VT; v++)
#pragma unroll
                        for (int i = 0; i < 8; i++)
                            acc[v][i] = fmaf(pv[v], wv[i], acc[v][i]);
                }
            }
        }
    }

    const size_t plane = (size_t)OUTS * OUTS;
#pragma unroll
    for (int i = 0; i < 8; i++) {
        float* yr = y + ((size_t)(n * COUT + cg + CG * i) * OUTS + od) * plane
                      + (oh0 + ohi) * OUTS + q;
#pragma unroll
        for (int v = 0; v < VT; v++) {
            float val = acc[v][i];
            if (RELU) val = fmaxf(val, 0.f);
            yr[Q * v] = val;
        }
    }
}

// ---------------------------------------------------------------------------
// VQ: per-position argmin over 512 codes, float4 codebook dots, per-tile norms.
// ---------------------------------------------------------------------------
__global__ void __launch_bounds__(128) vq_k(const float* __restrict__ cb,
        const float* __restrict__ ze, float* __restrict__ qo)
{
    __shared__ __align__(16) float4 cbs[128 * 16];   // 128 codes x 64 floats
    __shared__ float cbn_s[128];

    const int n = blockIdx.y;
    const int p = blockIdx.x * 128 + threadIdx.x;
    const int t = threadIdx.x;

    float z[64];
    const float* zb = ze + (size_t)n * 64 * 4096 + p;
#pragma unroll
    for (int c = 0; c < 64; c++) z[c] = zb[(size_t)c * 4096];

    float best = INFINITY;
    int bk = 0;
    const float4* cb4 = (const float4*)cb;
    for (int kt = 0; kt < 4; kt++) {
        __syncthreads();
        for (int idx = t; idx < 2048; idx += 128) cbs[idx] = cb4[kt * 2048 + idx];
        __syncthreads();
        {
            float s = 0.f;
#pragma unroll
            for (int j = 0; j < 16; j++) {
                float4 c = cbs[t * 16 + j];
                s = fmaf(c.x, c.x, s); s = fmaf(c.y, c.y, s);
                s = fmaf(c.z, c.z, s); s = fmaf(c.w, c.w, s);
            }
            cbn_s[t] = s;
        }
        __syncthreads();
        for (int kk = 0; kk < 128; kk++) {
            float d0 = 0.f, d1 = 0.f;
#pragma unroll
            for (int j = 0; j < 16; j++) {
                float4 c = cbs[kk * 16 + j];
                d0 = fmaf(z[4 * j + 0], c.x, d0);
                d1 = fmaf(z[4 * j + 1], c.y, d1);
                d0 = fmaf(z[4 * j + 2], c.z, d0);
                d1 = fmaf(z[4 * j + 3], c.w, d1);
            }
            float s = cbn_s[kk] - 2.f * (d0 + d1);
            if (s < best) { best = s; bk = kt * 128 + kk; }   // first-min tie-break
        }
    }

    float* qb = qo + (size_t)n * 64 * 4096 + p;
    const float* crow = cb + (size_t)bk * 64;
#pragma unroll
    for (int c = 0; c < 64; c++) qb[(size_t)c * 4096] = crow[c];
}

// ---------------------------------------------------------------------------
// transposed conv k4 s2 p1: y[o] += x[bd-kn] * w[k = p + 2kn]. Thread: VT
// voxels (ow = q + Q*v, parity-uniform since Q even) x 8 Cout.
// wsm groups padded to PWS = COUT+4 so even/odd-pw lanes hit distinct banks.
// ---------------------------------------------------------------------------
template <int CIN, int COUT, int INS, int OUTS, int CG, int Q, int OH_T, int CC, int ACT>
__global__ void __launch_bounds__(Q * CG * OH_T) convt_k(
    const float* __restrict__ x, const float* __restrict__ wT,
    const float* __restrict__ bias, float* __restrict__ y)
{
    constexpr int NT = Q * CG * OH_T;
    constexpr int VT = OUTS / Q;
    constexpr int IH = OH_T / 2 + 2;
    constexpr int PJ = OUTS / 2 + 2;
    constexpr int PWS = COUT + 4;

    __shared__ float wsm[CC * 32 * PWS];     // [cc][kdn][kh][kwn][pw][PWS]
    __shared__ float patch[CC * 2 * IH * PJ];

    const int od = blockIdx.x, oh0 = blockIdx.y * OH_T, n = blockIdx.z;
    const int t = threadIdx.x;
    const int q = t % Q;
    const int cg = (t / Q) % CG;
    const int ohi = t / (Q * CG);

    const int pd = (od + 1) & 1, bd = (od + 1) >> 1;
    const int pw = (q + 1) & 1,  bw0 = (q + 1) >> 1;
    const int ph = (ohi + 1) & 1;             // oh0 even
    const int rh = ((ohi + 1) >> 1) + 1;      // local bh row

    float acc[VT][8];
#pragma unroll
    for (int v = 0; v < VT; v++)
#pragma unroll
        for (int i = 0; i < 8; i++) acc[v][i] = bias[cg + CG * i];

    for (int ch = 0; ch < CIN / CC; ch++) {
        const int ci0 = ch * CC;
        __syncthreads();
        for (int idx = t; idx < CC * 32 * COUT; idx += NT) {
            int co  = idx % COUT;
            int r   = idx / COUT;
            int pww = r & 1;
            int kwn = (r >> 1) & 1;
            int kh  = (r >> 2) & 3;
            int kdn = (r >> 4) & 1;
            int cc  = r >> 5;
            int kd = pd + 2 * kdn, kw = pww + 2 * kwn;
            wsm[r * PWS + co] =
                wT[((ci0 + cc) * 64 + kd * 16 + kh * 4 + kw) * COUT + co];
        }
        for (int idx = t; idx < CC * 2 * IH * PJ; idx += NT) {
            int j  = idx % PJ;
            int r2 = idx / PJ;
            int r  = r2 % IH;
            int di = (r2 / IH) & 1;
            int cc = r2 / (IH * 2);
            int id = bd - di;
            int ih = oh0 / 2 - 1 + r;
            int iw = j - 1;
            float v = 0.f;
            if ((unsigned)id < (unsigned)INS && (unsigned)ih < (unsigned)INS &&
                (unsigned)iw < (unsigned)INS)
                v = x[((size_t)(n * CIN + ci0 + cc) * INS + id) * (INS * INS)
                      + ih * INS + iw];
            patch[idx] = v;
        }
        __syncthreads();

#pragma unroll 1
        for (int cc = 0; cc < CC; cc++) {
#pragma unroll
            for (int kdn = 0; kdn < 2; kdn++) {
#pragma unroll
                for (int khn = 0; khn < 2; khn++) {
                    const float* prow =
                        patch + ((cc * 2 + kdn) * IH + (rh - khn)) * PJ;
                    const int kh = ph + 2 * khn;
#pragma unroll
                    for (int kwn = 0; kwn < 2; kwn++) {
                        const float* wrow = wsm +
                            ((((cc * 2 + kdn) * 4 + kh) * 2 + kwn) * 2 + pw) * PWS + cg;
                        float wv[8];
#pragma unroll
                        for (int i = 0; i < 8; i++) wv[i] = wrow[CG * i];
                        float pv[VT];
#pragma unroll
                        for (int v = 0; v < VT; v++)
                            pv[v] = prow[bw0 + (Q / 2) * v - kwn + 1];
#pragma unroll
                        for (int v = 0; v < VT; v++)
#pragma unroll
                            for (int i = 0; i < 8; i++)
                                acc[v][i] = fmaf(pv[v], wv[i], acc[v][i]);
                    }
                }
            }
        }
    }

    const size_t plane = (size_t)OUTS * OUTS;
#pragma unroll
    for (int i = 0; i < 8; i++) {
        float* yr = y + ((size_t)(n * COUT + cg + CG * i) * OUTS + od) * plane
                      + (oh0 + ohi) * OUTS + q;
#pragma unroll
        for (int v = 0; v < VT; v++) {
            float val = acc[v][i];
            if (ACT == 1) val = fmaxf(val, 0.f);
            yr[Q * v] = val;
        }
    }
}

// ---------------------------------------------------------------------------
// convT3: 16->1, 64^3 -> 128^3, sigmoid. Thread computes 8 contiguous ow
// (ow = 8q + v): patch row kept in regs (float4+float2), all 4 kw weights in
// one float4 -> LDS:FMA ~ 10:16.
// ---------------------------------------------------------------------------
__global__ void __launch_bounds__(128) convt3_k(const float* __restrict__ x,
    const float* __restrict__ w, const float* __restrict__ bias,
    float* __restrict__ y)
{
    constexpr int CC = 8;
    constexpr int IH = 6;       // OH_T = 8
    constexpr int PJP = 68;     // 66 used cols, padded to mult-of-4

    __shared__ __align__(16) float wsm[16 * 64];
    __shared__ __align__(16) float patch[CC * 2 * IH * PJP];

    const int od = blockIdx.x, oh0 = blockIdx.y * 8, n = blockIdx.z;
    const int t = threadIdx.x;
    const int q = t & 15, ohi = t >> 4;

    const int pd = (od + 1) & 1, bd = (od + 1) >> 1;
    const int ph = (ohi + 1) & 1;
    const int rh = ((ohi + 1) >> 1) + 1;

    for (int idx = t; idx < 1024; idx += 128) wsm[idx] = w[idx];

    float acc[8];
    const float b0 = bias[0];
#pragma unroll
    for (int v = 0; v < 8; v++) acc[v] = b0;

    for (int ch = 0; ch < 2; ch++) {
        __syncthreads();
        for (int idx = t; idx < CC * 2 * IH * 66; idx += 128) {
            int j  = idx % 66;
            int r2 = idx / 66;
            int r  = r2 % IH;
            int di = (r2 / IH) & 1;
            int cc = r2 / (IH * 2);
            int id = bd - di;
            int ih = oh0 / 2 - 1 + r;
            int iw = j - 1;
            float v = 0.f;
            if ((unsigned)id < 64u && (unsigned)ih < 64u && (unsigned)iw < 64u)
                v = x[((size_t)(n * 16 + ch * CC + cc) * 64 + id) * 4096
                      + ih * 64 + iw];
            patch[r2 * PJP + j] = v;
        }
        __syncthreads();

#pragma unroll 1
        for (int cc = 0; cc < CC; cc++) {
#pragma unroll
            for (int kdn = 0; kdn < 2; kdn++) {
#pragma unroll
                for (int khn = 0; khn < 2; khn++) {
                    const int kd = pd + 2 * kdn, kh = ph + 2 * khn;
                    const float4 wq =
                        *(const float4*)&wsm[(ch * CC + cc) * 64 + kd * 16 + kh * 4];
                    const float* prow =
                        patch + ((cc * 2 + kdn) * IH + (rh - khn)) * PJP + 4 * q;
                    float4 pa = *(const float4*)prow;
                    float2 pb = *(const float2*)(prow + 4);
                    float p[6] = {pa.x, pa.y, pa.z, pa.w, pb.x, pb.y};
#pragma unroll
                    for (int v = 0; v < 8; v++) {
                        const int bwp = (v + 1) >> 1;
                        const float w0 = ((v + 1) & 1) ? wq.y : wq.x;  // kw = pw
                        const float w1 = ((v + 1) & 1) ? wq.w : wq.z;  // kw = pw+2
                        acc[v] = fmaf(p[bwp + 1], w0, acc[v]);
                        acc[v] = fmaf(p[bwp],     w1, acc[v]);
                    }
                }
            }
        }
    }

#pragma unroll
    for (int v = 0; v < 8; v++) {
        float s = 1.f / (1.f + __expf(-acc[v]));
        y[((size_t)n * 128 + od) * 16384 + (oh0 + ohi) * 128 + 8 * q + v] = s;
    }
}

// ---------------------------------------------------------------------------
extern "C" void kernel_launch(void* const* d_in, const int* in_sizes, int n_in,
                              void* d_out, int out_size)
{
    (void)in_sizes; (void)n_in; (void)out_size;

    const float* x   = (const float*)d_in[0];
    const float* w1  = (const float*)d_in[1];
    const float* b1  = (const float*)d_in[2];
    const float* w2  = (const float*)d_in[3];
    const float* b2  = (const float*)d_in[4];
    const float* w3  = (const float*)d_in[5];
    const float* b3  = (const float*)d_in[6];
    const float* cb  = (const float*)d_in[7];
    const float* dw1 = (const float*)d_in[8];
    const float* db1 = (const float*)d_in[9];
    const float* dw2 = (const float*)d_in[10];
    const float* db2 = (const float*)d_in[11];
    const float* dw3 = (const float*)d_in[12];
    const float* db3 = (const float*)d_in[13];

    float* out = (float*)d_out;
    float* x_hat = out;                 // 4*1*128^3   = 8388608
    float* qq    = out + 8388608;       // 4*64*16^3   = 1048576
    float* ze    = out + 9437184;       // 4*64*16^3   = 1048576

    float *h1, *h2, *dd1, *dd2, *wT;
    cudaGetSymbolAddress((void**)&h1,  g_h1);
    cudaGetSymbolAddress((void**)&h2,  g_h2);
    cudaGetSymbolAddress((void**)&dd1, g_d1);
    cudaGetSymbolAddress((void**)&dd2, g_d2);
    cudaGetSymbolAddress((void**)&wT,  g_wT);

    float* w1T  = wT;
    float* w2T  = wT + 1024;
    float* w3T  = wT + 33792;
    float* dw1T = wT + 164864;
    float* dw2T = wT + 295936;

    // weight transposes
    transp_oihw<<<(1024   + 255) / 256, 256>>>(w1,  w1T,  1,  16);
    transp_oihw<<<(32768  + 255) / 256, 256>>>(w2,  w2T,  16, 32);
    transp_oihw<<<(131072 + 255) / 256, 256>>>(w3,  w3T,  32, 64);
    transp_iohw<<<(131072 + 255) / 256, 256>>>(dw1, dw1T, 64, 32);
    transp_iohw<<<(32768  + 255) / 256, 256>>>(dw2, dw2T, 32, 16);

    // encoder
    conv_k<1, 16, 128, 64, 2, 16, 4, true ><<<dim3(64, 16, 4), 128>>>(x,  w1T, b1, h1);
    conv_k<16, 32, 64, 32, 4, 8,  4, true ><<<dim3(32, 8, 4),  128>>>(h1, w2T, b2, h2);
    conv_k<32, 64, 32, 16, 8, 4,  2, false><<<dim3(16, 8, 4),   64>>>(h2, w3T, b3, ze);

    // vector quantization
    vq_k<<<dim3(32, 4), 128>>>(cb, ze, qq);

    // decoder
    convt_k<64, 32, 16, 32, 4, 8,  4, 4, 1><<<dim3(32, 8, 4),  128>>>(qq,  dw1T, db1, dd1);
    convt_k<32, 16, 32, 64, 2, 16, 4, 8, 1><<<dim3(64, 16, 4), 128>>>(dd1, dw2T, db2, dd2);
    convt3_k<<<dim3(128, 16, 4), 128>>>(dd2, dw3, db3, x_hat);
}